// round 1
// baseline (speedup 1.0000x reference)
#include <cuda_runtime.h>
#include <math.h>

#define Nn   200000
#define Ee   3200000
#define Mm   100000
#define NEx  32
#define Cc   32
#define CHh  16
#define Hh   1024
#define NTt  11
#define Ll   8
#define EPSf 1e-5f

// ---------------- scratch (static device globals; no allocation) ----------------
__device__ __align__(128) float g_x[(size_t)Nn * 32];   // residual stream
__device__ __align__(128) float g_h[(size_t)Nn * 32];   // biconv temp (h1/h2)
__device__ __align__(128) float g_po[(size_t)Nn * 16];  // x @ w_out
__device__ __align__(128) float g_pb[(size_t)Nn * 16];  // x @ w_back
__device__ float g_s[Mm];
__device__ float g_stats[64];   // [0:32) sum, [32:64) sumsq
__device__ int   g_mx[NEx];     // ordered-int encoded segment max
__device__ float g_sum[NEx];    // segment sum of exp

__device__ __forceinline__ int fenc(float f) {
    int i = __float_as_int(f);
    return i >= 0 ? i : (i ^ 0x7FFFFFFF);
}
__device__ __forceinline__ float fdec(int i) {
    return __int_as_float(i >= 0 ? i : (i ^ 0x7FFFFFFF));
}

// ---------------- embed + first projection (also zeroes g_x) ----------------
__global__ __launch_bounds__(256) void k_embed(const int* __restrict__ nodes,
                                               const float* __restrict__ emb,
                                               const float* __restrict__ w_o,
                                               const float* __restrict__ w_b)
{
    __shared__ float semb[NTt * 32];
    __shared__ float swo[32 * 16], swb[32 * 16];
    for (int t = threadIdx.x; t < NTt * 32; t += blockDim.x) semb[t] = emb[t];
    for (int t = threadIdx.x; t < 512; t += blockDim.x) { swo[t] = w_o[t]; swb[t] = w_b[t]; }
    __syncthreads();

    int n = blockIdx.x * blockDim.x + threadIdx.x;
    if (n >= Nn) return;
    int ty = nodes[n];
    float tv[32];
#pragma unroll
    for (int c = 0; c < 32; c++) tv[c] = semb[ty * 32 + c];

    // zero g_x row (target of first edge scatter)
    float4 z = make_float4(0.f, 0.f, 0.f, 0.f);
    float4* xr = (float4*)(g_x + (size_t)n * 32);
#pragma unroll
    for (int q = 0; q < 8; q++) xr[q] = z;

    float o[16], b[16];
#pragma unroll
    for (int k = 0; k < 16; k++) { o[k] = 0.f; b[k] = 0.f; }
#pragma unroll 4
    for (int c = 0; c < 32; c++) {
        float tc = tv[c];
#pragma unroll
        for (int k = 0; k < 16; k++) {
            o[k] = fmaf(tc, swo[c * 16 + k], o[k]);
            b[k] = fmaf(tc, swb[c * 16 + k], b[k]);
        }
    }
    float4* po = (float4*)(g_po + (size_t)n * 16);
    float4* pb = (float4*)(g_pb + (size_t)n * 16);
#pragma unroll
    for (int q = 0; q < 4; q++) {
        po[q] = make_float4(o[q * 4], o[q * 4 + 1], o[q * 4 + 2], o[q * 4 + 3]);
        pb[q] = make_float4(b[q * 4], b[q * 4 + 1], b[q * 4 + 2], b[q * 4 + 3]);
    }
}

// ---------------- BN stats (mode 0: g_x; 1: g_x += g_h then stats; 2: g_h) ----------------
__global__ __launch_bounds__(256) void k_stats(int mode)
{
    int lane = threadIdx.x & 31;
    int gw = (blockIdx.x * blockDim.x + threadIdx.x) >> 5;
    int nw = (gridDim.x * blockDim.x) >> 5;
    float s = 0.f, q = 0.f;
    if (mode == 1) {
        for (int n = gw; n < Nn; n += nw) {
            size_t off = (size_t)n * 32 + lane;
            float v = g_x[off] + g_h[off];
            g_x[off] = v;
            s += v; q = fmaf(v, v, q);
        }
    } else {
        const float* x = (mode == 2) ? g_h : g_x;
        for (int n = gw; n < Nn; n += nw) {
            float v = x[(size_t)n * 32 + lane];
            s += v; q = fmaf(v, v, q);
        }
    }
    __shared__ float ss[32], sq[32];
    if (threadIdx.x < 32) { ss[threadIdx.x] = 0.f; sq[threadIdx.x] = 0.f; }
    __syncthreads();
    atomicAdd(&ss[lane], s);
    atomicAdd(&sq[lane], q);
    __syncthreads();
    if (threadIdx.x < 32) {
        atomicAdd(&g_stats[threadIdx.x], ss[threadIdx.x]);
        atomicAdd(&g_stats[32 + threadIdx.x], sq[threadIdx.x]);
    }
}

// ---------------- BN+relu+projection (also zeroes g_h for next edge pass) ----------------
__global__ __launch_bounds__(256) void k_proj(int srcsel,  // 0: read g_x, 1: read g_h
                                              const float* __restrict__ gamma,
                                              const float* __restrict__ beta,
                                              const float* __restrict__ w_o,
                                              const float* __restrict__ w_b)
{
    __shared__ float sA[32], sB[32];
    __shared__ float swo[512], swb[512];
    if (threadIdx.x < 32) {
        float m = g_stats[threadIdx.x] * (1.0f / Nn);
        float v = g_stats[32 + threadIdx.x] * (1.0f / Nn) - m * m;
        float a = gamma[threadIdx.x] * rsqrtf(v + EPSf);
        sA[threadIdx.x] = a;
        sB[threadIdx.x] = fmaf(-m, a, beta[threadIdx.x]);
    }
    for (int t = threadIdx.x; t < 512; t += blockDim.x) { swo[t] = w_o[t]; swb[t] = w_b[t]; }
    __syncthreads();

    int n = blockIdx.x * blockDim.x + threadIdx.x;
    if (n >= Nn) return;
    const float* xin = srcsel ? g_h : g_x;
    float tv[32];
    const float4* xr = (const float4*)(xin + (size_t)n * 32);
#pragma unroll
    for (int q = 0; q < 8; q++) {
        float4 v = xr[q];
        tv[q * 4 + 0] = fmaxf(fmaf(v.x, sA[q * 4 + 0], sB[q * 4 + 0]), 0.f);
        tv[q * 4 + 1] = fmaxf(fmaf(v.y, sA[q * 4 + 1], sB[q * 4 + 1]), 0.f);
        tv[q * 4 + 2] = fmaxf(fmaf(v.z, sA[q * 4 + 2], sB[q * 4 + 2]), 0.f);
        tv[q * 4 + 3] = fmaxf(fmaf(v.w, sA[q * 4 + 3], sB[q * 4 + 3]), 0.f);
    }
    // zero g_h row (row already consumed; next edge pass accumulates here)
    float4 z = make_float4(0.f, 0.f, 0.f, 0.f);
    float4* hz = (float4*)(g_h + (size_t)n * 32);
#pragma unroll
    for (int q = 0; q < 8; q++) hz[q] = z;

    float o[16], b[16];
#pragma unroll
    for (int k = 0; k < 16; k++) { o[k] = 0.f; b[k] = 0.f; }
#pragma unroll 4
    for (int c = 0; c < 32; c++) {
        float tc = tv[c];
#pragma unroll
        for (int k = 0; k < 16; k++) {
            o[k] = fmaf(tc, swo[c * 16 + k], o[k]);
            b[k] = fmaf(tc, swb[c * 16 + k], b[k]);
        }
    }
    float4* po = (float4*)(g_po + (size_t)n * 16);
    float4* pb = (float4*)(g_pb + (size_t)n * 16);
#pragma unroll
    for (int q = 0; q < 4; q++) {
        po[q] = make_float4(o[q * 4], o[q * 4 + 1], o[q * 4 + 2], o[q * 4 + 3]);
        pb[q] = make_float4(b[q * 4], b[q * 4 + 1], b[q * 4 + 2], b[q * 4 + 3]);
    }
}

// ---------------- edge scatter (both directions), 128-bit REDs ----------------
__global__ __launch_bounds__(256) void k_edge(int target,  // 0: acc into g_x, 1: g_h
                                              const int* __restrict__ src,
                                              const int* __restrict__ dst)
{
    if (blockIdx.x == 0) {  // piggyback scratch inits for downstream kernels
        if (threadIdx.x < 64) g_stats[threadIdx.x] = 0.f;
        if (threadIdx.x < NEx) { g_mx[threadIdx.x] = (int)0x80000000; g_sum[threadIdx.x] = 0.f; }
    }
    float4* acc = (float4*)(target ? g_h : g_x);
    const float4* po = (const float4*)g_po;
    const float4* pb = (const float4*)g_pb;
    int stride = gridDim.x * blockDim.x;
    for (int e = blockIdx.x * blockDim.x + threadIdx.x; e < Ee; e += stride) {
        int s = src[e], d = dst[e];
        const float4* a = po + (size_t)s * 4;
        float4 a0 = a[0], a1 = a[1], a2 = a[2], a3 = a[3];
        float4* ad = acc + (size_t)d * 8;           // out-half: channels 0..15
        atomicAdd(ad + 0, a0); atomicAdd(ad + 1, a1);
        atomicAdd(ad + 2, a2); atomicAdd(ad + 3, a3);
        const float4* b = pb + (size_t)d * 4;
        float4 b0 = b[0], b1 = b[1], b2 = b[2], b3 = b[3];
        float4* as = acc + (size_t)s * 8 + 4;       // back-half: channels 16..31
        atomicAdd(as + 0, b0); atomicAdd(as + 1, b1);
        atomicAdd(as + 2, b2); atomicAdd(as + 3, b3);
    }
}

// ---------------- head MLP: s = relu(relu(x_sel)@wh + bh) @ wo + bo ----------------
__global__ __launch_bounds__(256) void k_head(const int* __restrict__ indices,
                                              const int* __restrict__ assign,
                                              const float* __restrict__ wh,
                                              const float* __restrict__ bh,
                                              const float* __restrict__ wo,
                                              const float* __restrict__ bo)
{
    __shared__ float ws[32 * 64];
    __shared__ float sbh[64], swo2[64];
    int i = blockIdx.x * blockDim.x + threadIdx.x;
    float r[32];
    int seg = 0;
    bool valid = (i < Mm);
    if (valid) {
        int idx = indices[i];
        seg = assign[idx];
        const float4* a = (const float4*)(g_x + (size_t)idx * 32);  // final residual =
        const float4* b = (const float4*)(g_h + (size_t)idx * 32);  // g_x + last h2 (fused here)
#pragma unroll
        for (int q = 0; q < 8; q++) {
            float4 u = a[q], v = b[q];
            r[q * 4 + 0] = fmaxf(u.x + v.x, 0.f);
            r[q * 4 + 1] = fmaxf(u.y + v.y, 0.f);
            r[q * 4 + 2] = fmaxf(u.z + v.z, 0.f);
            r[q * 4 + 3] = fmaxf(u.w + v.w, 0.f);
        }
    } else {
#pragma unroll
        for (int c = 0; c < 32; c++) r[c] = 0.f;
    }
    float acc = 0.f;
    for (int j0 = 0; j0 < Hh; j0 += 64) {
        __syncthreads();
        for (int t = threadIdx.x; t < 32 * 64; t += blockDim.x) {
            int c = t >> 6, jj = t & 63;
            ws[t] = wh[c * Hh + j0 + jj];
        }
        if (threadIdx.x < 64) {
            sbh[threadIdx.x] = bh[j0 + threadIdx.x];
            swo2[threadIdx.x] = wo[j0 + threadIdx.x];
        }
        __syncthreads();
#pragma unroll 2
        for (int jj = 0; jj < 64; jj++) {
            float z = sbh[jj];
#pragma unroll
            for (int c = 0; c < 32; c++) z = fmaf(r[c], ws[c * 64 + jj], z);
            acc = fmaf(fmaxf(z, 0.f), swo2[jj], acc);
        }
    }
    if (valid) {
        float s = acc + bo[0];
        g_s[i] = s;
        atomicMax(&g_mx[seg], fenc(s));
    }
}

// ---------------- segment sum of exp (seg is sorted -> shared pre-reduction) ----------------
__global__ __launch_bounds__(256) void k_lse(const int* __restrict__ indices,
                                             const int* __restrict__ assign)
{
    __shared__ float part[NEx];
    if (threadIdx.x < NEx) part[threadIdx.x] = 0.f;
    __syncthreads();
    int i = blockIdx.x * blockDim.x + threadIdx.x;
    if (i < Mm) {
        int seg = assign[indices[i]];
        float e = expf(g_s[i] - fdec(g_mx[seg]));
        atomicAdd(&part[seg], e);
    }
    __syncthreads();
    if (threadIdx.x < NEx && part[threadIdx.x] != 0.f)
        atomicAdd(&g_sum[threadIdx.x], part[threadIdx.x]);
}

__global__ __launch_bounds__(256) void k_out(const int* __restrict__ indices,
                                             const int* __restrict__ assign,
                                             float* __restrict__ out)
{
    int i = blockIdx.x * blockDim.x + threadIdx.x;
    if (i >= Mm) return;
    int seg = assign[indices[i]];
    out[i] = g_s[i] - fdec(g_mx[seg]) - logf(g_sum[seg]);
}

// ---------------- launch ----------------
extern "C" void kernel_launch(void* const* d_in, const int* in_sizes, int n_in,
                              void* d_out, int out_size)
{
    // robust to num_examples scalar being included (n_in==21) or not (n_in==20)
    int o = n_in - 20;
    const int*   assignment = (const int*)d_in[o + 0];
    const int*   nodes      = (const int*)d_in[o + 1];
    const int*   src        = (const int*)d_in[o + 2];
    const int*   dst        = (const int*)d_in[o + 3];
    const int*   indices    = (const int*)d_in[o + 4];
    const float* emb        = (const float*)d_in[o + 5];
    const float* w0o        = (const float*)d_in[o + 6];
    const float* w0b        = (const float*)d_in[o + 7];
    const float* bn1g       = (const float*)d_in[o + 8];
    const float* bn1b       = (const float*)d_in[o + 9];
    const float* w1o        = (const float*)d_in[o + 10];
    const float* w1b        = (const float*)d_in[o + 11];
    const float* bn2g       = (const float*)d_in[o + 12];
    const float* bn2b       = (const float*)d_in[o + 13];
    const float* w2o        = (const float*)d_in[o + 14];
    const float* w2b        = (const float*)d_in[o + 15];
    const float* wh         = (const float*)d_in[o + 16];
    const float* bh         = (const float*)d_in[o + 17];
    const float* wo         = (const float*)d_in[o + 18];
    const float* bo         = (const float*)d_in[o + 19];
    float* out = (float*)d_out;

    const int nb = (Nn + 255) / 256;
    const int eb = (Ee + 255) / 256;
    const int mb = (Mm + 255) / 256;

    k_embed<<<nb, 256>>>(nodes, emb, w0o, w0b);
    k_edge<<<eb, 256>>>(0, src, dst);   // x = biconv0 (into g_x); zeroes g_stats
    for (int l = 0; l < Ll; l++) {
        k_stats<<<232, 256>>>(l == 0 ? 0 : 1);                 // (x += h2), stats(x)
        k_proj<<<nb, 256>>>(0, bn1g + l * 32, bn1b + l * 32,
                            w1o + l * 512, w1b + l * 512);      // t1 proj; zero g_h
        k_edge<<<eb, 256>>>(1, src, dst);                       // h1 into g_h
        k_stats<<<232, 256>>>(2);                               // stats(h1)
        k_proj<<<nb, 256>>>(1, bn2g + l * 32, bn2b + l * 32,
                            w2o + l * 512, w2b + l * 512);      // t2 proj; re-zero g_h
        k_edge<<<eb, 256>>>(1, src, dst);                       // h2 into g_h
    }
    k_head<<<mb, 256>>>(indices, assignment, wh, bh, wo, bo);
    k_lse<<<mb, 256>>>(indices, assignment);
    k_out<<<mb, 256>>>(indices, assignment, out);
}

// round 2
// speedup vs baseline: 1.5760x; 1.5760x over previous
#include <cuda_runtime.h>
#include <math.h>

#define Nn   200000
#define Ee   3200000
#define Mm   100000
#define NEx  32
#define Hh   1024
#define NTt  11
#define Ll   8
#define EPSf 1e-5f

#define NPASS 17
#define NB2   196        // ceil(Nn / 1024) scan blocks
#define GB    1184       // gather grid

// ---------------- scratch (static device globals; no allocation) ----------------
__device__ __align__(128) float g_x[(size_t)Nn * 32];   // residual stream
__device__ __align__(128) float g_h[(size_t)Nn * 32];   // biconv temp (h1)
__device__ __align__(128) float g_po[(size_t)Nn * 16];  // x @ w_out
__device__ __align__(128) float g_pb[(size_t)Nn * 16];  // x @ w_back
__device__ float g_s[Mm];
__device__ float g_statsA[NPASS * 64];  // per-pass: [0:32) sum, [32:64) sumsq
__device__ int   g_mx[NEx];
__device__ float g_sum[NEx];

// CSR scratch
__device__ int g_cnt_out[Nn], g_cnt_in[Nn];
__device__ int g_rout[Nn + 1], g_rin[Nn + 1];
__device__ int g_cur_out[Nn], g_cur_in[Nn];
__device__ int g_adj_out[Ee];   // for each dst-sorted slot: src id
__device__ int g_adj_in[Ee];    // for each src-sorted slot: dst id
__device__ int g_bsum[2][256];

__device__ __forceinline__ int fenc(float f) {
    int i = __float_as_int(f);
    return i >= 0 ? i : (i ^ 0x7FFFFFFF);
}
__device__ __forceinline__ float fdec(int i) {
    return __int_as_float(i >= 0 ? i : (i ^ 0x7FFFFFFF));
}

// ---------------- embed + first projection; also zero counters/stats ----------------
__global__ __launch_bounds__(256) void k_embed(const int* __restrict__ nodes,
                                               const float* __restrict__ emb,
                                               const float* __restrict__ w_o,
                                               const float* __restrict__ w_b)
{
    __shared__ float semb[NTt * 32];
    __shared__ float swo[512], swb[512];
    for (int t = threadIdx.x; t < NTt * 32; t += blockDim.x) semb[t] = emb[t];
    for (int t = threadIdx.x; t < 512; t += blockDim.x) { swo[t] = w_o[t]; swb[t] = w_b[t]; }
    if (blockIdx.x == 0) {
        for (int t = threadIdx.x; t < NPASS * 64; t += blockDim.x) g_statsA[t] = 0.f;
        if (threadIdx.x < NEx) { g_mx[threadIdx.x] = (int)0x80000000; g_sum[threadIdx.x] = 0.f; }
    }
    __syncthreads();

    int n = blockIdx.x * blockDim.x + threadIdx.x;
    if (n >= Nn) return;
    g_cnt_out[n] = 0;
    g_cnt_in[n] = 0;
    int ty = nodes[n];
    float tv[32];
#pragma unroll
    for (int c = 0; c < 32; c++) tv[c] = semb[ty * 32 + c];

    float o[16], b[16];
#pragma unroll
    for (int k = 0; k < 16; k++) { o[k] = 0.f; b[k] = 0.f; }
#pragma unroll 4
    for (int c = 0; c < 32; c++) {
        float tc = tv[c];
#pragma unroll
        for (int k = 0; k < 16; k++) {
            o[k] = fmaf(tc, swo[c * 16 + k], o[k]);
            b[k] = fmaf(tc, swb[c * 16 + k], b[k]);
        }
    }
    float4* po = (float4*)(g_po + (size_t)n * 16);
    float4* pb = (float4*)(g_pb + (size_t)n * 16);
#pragma unroll
    for (int q = 0; q < 4; q++) {
        po[q] = make_float4(o[q * 4], o[q * 4 + 1], o[q * 4 + 2], o[q * 4 + 3]);
        pb[q] = make_float4(b[q * 4], b[q * 4 + 1], b[q * 4 + 2], b[q * 4 + 3]);
    }
}

// ---------------- CSR build ----------------
__global__ __launch_bounds__(256) void k_hist(const int* __restrict__ src,
                                              const int* __restrict__ dst)
{
    int e = blockIdx.x * blockDim.x + threadIdx.x;
    if (e >= Ee) return;
    atomicAdd(&g_cnt_out[dst[e]], 1);
    atomicAdd(&g_cnt_in[src[e]], 1);
}

__global__ __launch_bounds__(256) void k_scan1()
{
    int a = blockIdx.y;
    const int* cnt = a ? g_cnt_in : g_cnt_out;
    int base = blockIdx.x * 1024 + threadIdx.x * 4;
    int s = 0;
#pragma unroll
    for (int i = 0; i < 4; i++) { int id = base + i; if (id < Nn) s += cnt[id]; }
    __shared__ int sh[256];
    sh[threadIdx.x] = s;
    __syncthreads();
    for (int off = 128; off > 0; off >>= 1) {
        if (threadIdx.x < off) sh[threadIdx.x] += sh[threadIdx.x + off];
        __syncthreads();
    }
    if (threadIdx.x == 0) g_bsum[a][blockIdx.x] = sh[0];
}

__global__ __launch_bounds__(256) void k_scan2()
{
    int a = blockIdx.x;
    __shared__ int sh[256];
    int v = (threadIdx.x < NB2) ? g_bsum[a][threadIdx.x] : 0;
    sh[threadIdx.x] = v;
    __syncthreads();
    for (int off = 1; off < 256; off <<= 1) {
        int u = (threadIdx.x >= off) ? sh[threadIdx.x - off] : 0;
        __syncthreads();
        sh[threadIdx.x] += u;
        __syncthreads();
    }
    if (threadIdx.x < NB2) g_bsum[a][threadIdx.x] = sh[threadIdx.x] - v;  // exclusive
    if (threadIdx.x == 0) { if (a) g_rin[Nn] = Ee; else g_rout[Nn] = Ee; }
}

__global__ __launch_bounds__(256) void k_scan3()
{
    int a = blockIdx.y;
    const int* cnt = a ? g_cnt_in : g_cnt_out;
    int* rptr = a ? g_rin : g_rout;
    int* cur  = a ? g_cur_in : g_cur_out;
    int base = blockIdx.x * 1024 + threadIdx.x * 4;
    int c4[4], pre[4];
    int s = 0;
#pragma unroll
    for (int i = 0; i < 4; i++) {
        int id = base + i;
        c4[i] = (id < Nn) ? cnt[id] : 0;
        pre[i] = s;
        s += c4[i];
    }
    __shared__ int sh[256];
    sh[threadIdx.x] = s;
    __syncthreads();
    for (int off = 1; off < 256; off <<= 1) {
        int u = (threadIdx.x >= off) ? sh[threadIdx.x - off] : 0;
        __syncthreads();
        sh[threadIdx.x] += u;
        __syncthreads();
    }
    int toff = sh[threadIdx.x] - s + g_bsum[a][blockIdx.x];
#pragma unroll
    for (int i = 0; i < 4; i++) {
        int id = base + i;
        if (id < Nn) { int p = toff + pre[i]; rptr[id] = p; cur[id] = p; }
    }
}

__global__ __launch_bounds__(256) void k_scatter(const int* __restrict__ src,
                                                 const int* __restrict__ dst)
{
    int e = blockIdx.x * blockDim.x + threadIdx.x;
    if (e >= Ee) return;
    int s = src[e], d = dst[e];
    g_adj_out[atomicAdd(&g_cur_out[d], 1)] = s;
    g_adj_in[atomicAdd(&g_cur_in[s], 1)] = d;
}

// ---------------- gather aggregation + fused residual + fused BN stats ----------------
// mode 0: g_x = agg             (first biconv)
// mode 1: g_h = agg             (h1)
// mode 2: g_x += agg            (h2 + residual)
// Warp-per-node: lanes 0-15 = out-direction channels, lanes 16-31 = back-direction.
__global__ __launch_bounds__(256) void k_gather(int mode, int pass)
{
    int lane = threadIdx.x & 31;
    int half = lane >> 4;
    int c = lane & 15;
    int warp = threadIdx.x >> 5;
    const int* rp = half ? g_rin : g_rout;
    const int* adj = half ? g_adj_in : g_adj_out;
    const float* tab = half ? g_pb : g_po;
    unsigned hm = half ? 0xFFFF0000u : 0x0000FFFFu;
    int sbase = half << 4;

    float ssum = 0.f, ssq = 0.f;
    for (int n = blockIdx.x * 8 + warp; n < Nn; n += gridDim.x * 8) {
        int base = rp[n], end = rp[n + 1];
        float acc = 0.f;
        for (int j0 = base; j0 < end; j0 += 16) {
            int idx = j0 + c;
            int myn = (idx < end) ? adj[idx] : 0;
            int cnt = min(16, end - j0);
#pragma unroll 4
            for (int t = 0; t < cnt; t++) {
                int nbr = __shfl_sync(hm, myn, sbase + t);
                acc += tab[(size_t)nbr * 16 + c];
            }
        }
        size_t off = (size_t)n * 32 + lane;
        float v = acc;
        if (mode == 2) v += g_x[off];
        if (mode == 1) g_h[off] = v; else g_x[off] = v;
        ssum += v;
        ssq = fmaf(v, v, ssq);
    }
    __shared__ float ss[64];
    if (threadIdx.x < 64) ss[threadIdx.x] = 0.f;
    __syncthreads();
    atomicAdd(&ss[lane], ssum);
    atomicAdd(&ss[32 + lane], ssq);
    __syncthreads();
    if (threadIdx.x < 64) atomicAdd(&g_statsA[pass * 64 + threadIdx.x], ss[threadIdx.x]);
}

// ---------------- BN+relu+projection (2 threads per node: one per matrix) ----------------
__global__ __launch_bounds__(256) void k_proj(int srcsel, int pass,
                                              const float* __restrict__ gamma,
                                              const float* __restrict__ beta,
                                              const float* __restrict__ w_o,
                                              const float* __restrict__ w_b)
{
    __shared__ float sA[32], sB[32];
    __shared__ float sw[2][512];
    if (threadIdx.x < 32) {
        float m = g_statsA[pass * 64 + threadIdx.x] * (1.0f / Nn);
        float v = g_statsA[pass * 64 + 32 + threadIdx.x] * (1.0f / Nn) - m * m;
        float a = gamma[threadIdx.x] * rsqrtf(v + EPSf);
        sA[threadIdx.x] = a;
        sB[threadIdx.x] = fmaf(-m, a, beta[threadIdx.x]);
    }
    for (int t = threadIdx.x; t < 512; t += blockDim.x) { sw[0][t] = w_o[t]; sw[1][t] = w_b[t]; }
    __syncthreads();

    int gid = blockIdx.x * blockDim.x + threadIdx.x;
    int n = gid >> 1, m = gid & 1;
    if (n >= Nn) return;
    const float* xin = srcsel ? g_h : g_x;
    float tv[32];
    const float4* xr = (const float4*)(xin + (size_t)n * 32);
#pragma unroll
    for (int q = 0; q < 8; q++) {
        float4 v = xr[q];
        tv[q * 4 + 0] = fmaxf(fmaf(v.x, sA[q * 4 + 0], sB[q * 4 + 0]), 0.f);
        tv[q * 4 + 1] = fmaxf(fmaf(v.y, sA[q * 4 + 1], sB[q * 4 + 1]), 0.f);
        tv[q * 4 + 2] = fmaxf(fmaf(v.z, sA[q * 4 + 2], sB[q * 4 + 2]), 0.f);
        tv[q * 4 + 3] = fmaxf(fmaf(v.w, sA[q * 4 + 3], sB[q * 4 + 3]), 0.f);
    }
    float o[16];
#pragma unroll
    for (int k = 0; k < 16; k++) o[k] = 0.f;
    const float* w = sw[m];
#pragma unroll 4
    for (int c = 0; c < 32; c++) {
        float tc = tv[c];
#pragma unroll
        for (int k = 0; k < 16; k++) o[k] = fmaf(tc, w[c * 16 + k], o[k]);
    }
    float4* outp = (float4*)((m ? g_pb : g_po) + (size_t)n * 16);
#pragma unroll
    for (int q = 0; q < 4; q++)
        outp[q] = make_float4(o[q * 4], o[q * 4 + 1], o[q * 4 + 2], o[q * 4 + 3]);
}

// ---------------- head MLP ----------------
__global__ __launch_bounds__(256) void k_head(const int* __restrict__ indices,
                                              const int* __restrict__ assign,
                                              const float* __restrict__ wh,
                                              const float* __restrict__ bh,
                                              const float* __restrict__ wo,
                                              const float* __restrict__ bo)
{
    __shared__ float ws[32 * 64];
    __shared__ float sbh[64], swo2[64];
    int i = blockIdx.x * blockDim.x + threadIdx.x;
    float r[32];
    int seg = 0;
    bool valid = (i < Mm);
    if (valid) {
        int idx = indices[i];
        seg = assign[idx];
        const float4* a = (const float4*)(g_x + (size_t)idx * 32);
#pragma unroll
        for (int q = 0; q < 8; q++) {
            float4 u = a[q];
            r[q * 4 + 0] = fmaxf(u.x, 0.f);
            r[q * 4 + 1] = fmaxf(u.y, 0.f);
            r[q * 4 + 2] = fmaxf(u.z, 0.f);
            r[q * 4 + 3] = fmaxf(u.w, 0.f);
        }
    } else {
#pragma unroll
        for (int c = 0; c < 32; c++) r[c] = 0.f;
    }
    float acc = 0.f;
    for (int j0 = 0; j0 < Hh; j0 += 64) {
        __syncthreads();
        for (int t = threadIdx.x; t < 32 * 64; t += blockDim.x) {
            int c = t >> 6, jj = t & 63;
            ws[t] = wh[c * Hh + j0 + jj];
        }
        if (threadIdx.x < 64) {
            sbh[threadIdx.x] = bh[j0 + threadIdx.x];
            swo2[threadIdx.x] = wo[j0 + threadIdx.x];
        }
        __syncthreads();
#pragma unroll 2
        for (int jj = 0; jj < 64; jj++) {
            float z = sbh[jj];
#pragma unroll
            for (int c = 0; c < 32; c++) z = fmaf(r[c], ws[c * 64 + jj], z);
            acc = fmaf(fmaxf(z, 0.f), swo2[jj], acc);
        }
    }
    if (valid) {
        float s = acc + bo[0];
        g_s[i] = s;
        atomicMax(&g_mx[seg], fenc(s));
    }
}

__global__ __launch_bounds__(256) void k_lse(const int* __restrict__ indices,
                                             const int* __restrict__ assign)
{
    __shared__ float part[NEx];
    if (threadIdx.x < NEx) part[threadIdx.x] = 0.f;
    __syncthreads();
    int i = blockIdx.x * blockDim.x + threadIdx.x;
    if (i < Mm) {
        int seg = assign[indices[i]];
        float e = expf(g_s[i] - fdec(g_mx[seg]));
        atomicAdd(&part[seg], e);
    }
    __syncthreads();
    if (threadIdx.x < NEx && part[threadIdx.x] != 0.f)
        atomicAdd(&g_sum[threadIdx.x], part[threadIdx.x]);
}

__global__ __launch_bounds__(256) void k_out(const int* __restrict__ indices,
                                             const int* __restrict__ assign,
                                             float* __restrict__ out)
{
    int i = blockIdx.x * blockDim.x + threadIdx.x;
    if (i >= Mm) return;
    int seg = assign[indices[i]];
    out[i] = g_s[i] - fdec(g_mx[seg]) - logf(g_sum[seg]);
}

// ---------------- launch ----------------
extern "C" void kernel_launch(void* const* d_in, const int* in_sizes, int n_in,
                              void* d_out, int out_size)
{
    int o = n_in - 20;
    const int*   assignment = (const int*)d_in[o + 0];
    const int*   nodes      = (const int*)d_in[o + 1];
    const int*   src        = (const int*)d_in[o + 2];
    const int*   dst        = (const int*)d_in[o + 3];
    const int*   indices    = (const int*)d_in[o + 4];
    const float* emb        = (const float*)d_in[o + 5];
    const float* w0o        = (const float*)d_in[o + 6];
    const float* w0b        = (const float*)d_in[o + 7];
    const float* bn1g       = (const float*)d_in[o + 8];
    const float* bn1b       = (const float*)d_in[o + 9];
    const float* w1o        = (const float*)d_in[o + 10];
    const float* w1b        = (const float*)d_in[o + 11];
    const float* bn2g       = (const float*)d_in[o + 12];
    const float* bn2b       = (const float*)d_in[o + 13];
    const float* w2o        = (const float*)d_in[o + 14];
    const float* w2b        = (const float*)d_in[o + 15];
    const float* wh         = (const float*)d_in[o + 16];
    const float* bh         = (const float*)d_in[o + 17];
    const float* wo         = (const float*)d_in[o + 18];
    const float* bo         = (const float*)d_in[o + 19];
    float* out = (float*)d_out;

    const int nb = (Nn + 255) / 256;
    const int eb = (Ee + 255) / 256;
    const int mb = (Mm + 255) / 256;
    const int pbgrid = (2 * Nn + 255) / 256;

    // embed + zero counters/stats; build CSR (both directions)
    k_embed<<<nb, 256>>>(nodes, emb, w0o, w0b);
    k_hist<<<eb, 256>>>(src, dst);
    { dim3 g(NB2, 2); k_scan1<<<g, 256>>>(); }
    k_scan2<<<2, 256>>>();
    { dim3 g(NB2, 2); k_scan3<<<g, 256>>>(); }
    k_scatter<<<eb, 256>>>(src, dst);

    // x0 = biconv(emb) (+stats set 0)
    k_gather<<<GB, 256>>>(0, 0);
    for (int l = 0; l < Ll; l++) {
        k_proj<<<pbgrid, 256>>>(0, 2 * l, bn1g + l * 32, bn1b + l * 32,
                                w1o + l * 512, w1b + l * 512);
        k_gather<<<GB, 256>>>(1, 2 * l + 1);            // h1 (+stats)
        k_proj<<<pbgrid, 256>>>(1, 2 * l + 1, bn2g + l * 32, bn2b + l * 32,
                                w2o + l * 512, w2b + l * 512);
        k_gather<<<GB, 256>>>(2, 2 * l + 2);            // x += h2 (+stats)
    }
    k_head<<<mb, 256>>>(indices, assignment, wh, bh, wo, bo);
    k_lse<<<mb, 256>>>(indices, assignment);
    k_out<<<mb, 256>>>(indices, assignment, out);
}